// round 8
// baseline (speedup 1.0000x reference)
#include <cuda_runtime.h>

#define BB   4
#define SS   2048
#define DD   10
#define VV   32000
#define ROWS (BB*SS)
#define RPB  128       // rows per logits block
#define HST  12        // padded h stride (floats) for LDS.128

// scratch (device globals — no allocation allowed)
__device__ float g_Q [ROWS*DD];
__device__ float g_KV[ROWS*20];    // K (0..9) and V (10..19) interleaved, 80B/row
__device__ float g_O [ROWS*DD];

// packed f32x2 FMA (Blackwell FFMA2)
__device__ __forceinline__ float2 ffma2(float2 a, float2 b, float2 c) {
    float2 d;
    asm("fma.rn.f32x2 %0, %1, %2, %3;"
        : "=l"(reinterpret_cast<unsigned long long&>(d))
        : "l"(reinterpret_cast<unsigned long long&>(a)),
          "l"(reinterpret_cast<unsigned long long&>(b)),
          "l"(reinterpret_cast<unsigned long long&>(c)));
    return d;
}

// two no-ops: keeps the ncu capture slot (launch #6) on attn_kernel
__global__ void noop_kernel() {}

// ---------------------------------------------------------------------------
// Kernel 1: h = emb[x] + pos;  G = h @ W.T  for one of {Q,K,V} per blockIdx.y.
// K and V now write into the interleaved g_KV layout (80 B per row) so the
// attention kernel can fetch a full K+V row with 5 broadcast LDG.128.
// ---------------------------------------------------------------------------
__global__ void __launch_bounds__(128) qkv_kernel(
    const int* __restrict__ x, const float* __restrict__ emb,
    const float* __restrict__ pos, const float* __restrict__ Wq,
    const float* __restrict__ Wk, const float* __restrict__ Wv)
{
    __shared__ float sw[DD*DD];
    const float* W = (blockIdx.y == 0) ? Wq : (blockIdx.y == 1) ? Wk : Wv;

    if (threadIdx.x < DD*DD/2)
        ((float2*)sw)[threadIdx.x] = __ldg((const float2*)W + threadIdx.x);

    int row = blockIdx.x * 128 + threadIdx.x;
    int s   = row & (SS - 1);
    int tok = x[row];

    float2 h2[5];
    const float2* ep = (const float2*)(emb + tok*DD);
    const float2* pp = (const float2*)(pos + s*DD);
#pragma unroll
    for (int e = 0; e < 5; e++) {
        float2 ee = __ldg(ep + e), qq = __ldg(pp + e);
        h2[e] = make_float2(ee.x + qq.x, ee.y + qq.y);
    }
    __syncthreads();

    float* gout = (blockIdx.y == 0) ? (g_Q + row*DD)
                : (blockIdx.y == 1) ? (g_KV + row*20)
                                    : (g_KV + row*20 + DD);
    float2* go = (float2*)gout;
#pragma unroll
    for (int d = 0; d < DD; d += 2) {
        float2 s0 = make_float2(0.f, 0.f), s1 = s0;
        const float2* w0 = (const float2*)(sw + d*DD);
        const float2* w1 = (const float2*)(sw + (d+1)*DD);
#pragma unroll
        for (int e = 0; e < 5; e++) {
            s0 = ffma2(h2[e], w0[e], s0);
            s1 = ffma2(h2[e], w1[e], s1);
        }
        go[d >> 1] = make_float2(s0.x + s0.y, s1.x + s1.y);
    }
}

// ---------------------------------------------------------------------------
// Kernel 2: causal attention — one THREAD per output row, t-range split 8x.
// Block (k,b): 8 warps = 8 equal t-chunks (len 4k+4) of row-group k
// (rows 32k..32k+31 of batch b). All lanes of a warp walk the same t ->
// K/V loads are broadcast LDG.128. No shuffles; chunks combine via shared
// in fixed order (deterministic). Longest warp chain: 256 iters (was 2047).
// Masked t (t > s) skipped == reference's exp(-1e9/sqrt(d)) == 0 in f32.
// ---------------------------------------------------------------------------
__global__ void __launch_bounds__(256) attn_kernel()
{
    __shared__ float sh [8*32*11];
    __shared__ float sh2[32*11];

    int b    = blockIdx.y;
    int k    = 63 - blockIdx.x;          // heavy-first
    int c    = threadIdx.x >> 5;         // chunk 0..7
    int lane = threadIdx.x & 31;
    const float inv_sqrt_d = 0.3162277660168379f;

    int s0   = k * 32;
    int slim = s0 + lane;                // causal limit for this row
    int rowg = b*SS + s0 + lane;

    float2 q2[5];
    const float2* qp = (const float2*)(g_Q + rowg*DD);
#pragma unroll
    for (int e = 0; e < 5; e++) q2[e] = qp[e];

    int niter = 4*k + 4;
    int t0    = c * niter;
    const float4* kvb = (const float4*)(g_KV + (size_t)b*SS*20);

    float  l = 0.f;
    float2 acc[5];
#pragma unroll
    for (int e = 0; e < 5; e++) acc[e] = make_float2(0.f, 0.f);

#pragma unroll 2
    for (int t = t0; t < t0 + niter; t++) {
        const float4* kv = kvb + (size_t)t * 5;
        float4 A = kv[0], B = kv[1], C = kv[2], D4 = kv[3], E = kv[4];
        float2 s2 = make_float2(0.f, 0.f);
        s2 = ffma2(q2[0], make_float2(A.x, A.y), s2);
        s2 = ffma2(q2[1], make_float2(A.z, A.w), s2);
        s2 = ffma2(q2[2], make_float2(B.x, B.y), s2);
        s2 = ffma2(q2[3], make_float2(B.z, B.w), s2);
        s2 = ffma2(q2[4], make_float2(C.x, C.y), s2);
        if (t <= slim) {
            float ex = __expf((s2.x + s2.y) * inv_sqrt_d);
            l += ex;
            float2 e2 = make_float2(ex, ex);
            acc[0] = ffma2(make_float2(C.z, C.w),  e2, acc[0]);
            acc[1] = ffma2(make_float2(D4.x, D4.y), e2, acc[1]);
            acc[2] = ffma2(make_float2(D4.z, D4.w), e2, acc[2]);
            acc[3] = ffma2(make_float2(E.x, E.y),  e2, acc[3]);
            acc[4] = ffma2(make_float2(E.z, E.w),  e2, acc[4]);
        }
    }

    // stage partials: (chunk, row) -> 11 floats; stride 11 is conflict-free
    float* p = sh + (c*32 + lane)*11;
    p[0] = l;
#pragma unroll
    for (int e = 0; e < 5; e++) { p[1 + 2*e] = acc[e].x; p[2 + 2*e] = acc[e].y; }
    __syncthreads();

    // combine 8 chunks in fixed order
    for (int i = threadIdx.x; i < 32*11; i += 256) {
        float s = 0.f;
#pragma unroll
        for (int cc = 0; cc < 8; cc++) s += sh[(cc*32)*11 + i];
        sh2[i] = s;
    }
    __syncthreads();

    // normalize + store
    for (int i = threadIdx.x; i < 32*DD; i += 256) {
        int r = i / DD, d = i - r*DD;
        g_O[(b*SS + s0 + r)*DD + d] = sh2[r*11 + 1 + d] / sh2[r*11];
    }
}

// ---------------------------------------------------------------------------
// Kernel 3: logits = out @ Wo.T — EXACT R5 version (best measured: 163.5us,
// DRAM 76%). 3 LDS.128 (padded) + 40 FFMA2 + 2 dense STG.128 per (warp,row).
// ---------------------------------------------------------------------------
__global__ void __launch_bounds__(160) logits_kernel(
    const float* __restrict__ Wo, float* __restrict__ out)
{
    __shared__ float sh[RPB*HST];
    int r0   = blockIdx.x * RPB;
    int tid  = threadIdx.x;
    int warp = tid >> 5;
    int lane = tid & 31;

    for (int i = tid; i < RPB*DD; i += 160) {
        int row = i / DD, d = i - row*DD;
        sh[row*HST + d] = g_O[r0*DD + i];
    }
    __syncthreads();

    int vbase = (blockIdx.y * 5 + warp) * 256 + lane * 4;

    float2 w[2][2][DD];   // [chunk][pair][d]
#pragma unroll
    for (int c = 0; c < 2; c++)
#pragma unroll
        for (int p = 0; p < 2; p++)
#pragma unroll
            for (int d = 0; d < DD; d++) {
                int v = vbase + c*128 + 2*p;
                w[c][p][d].x = __ldg(Wo + (v    )*DD + d);
                w[c][p][d].y = __ldg(Wo + (v + 1)*DD + d);
            }

#pragma unroll 1
    for (int s = 0; s < RPB; s++) {
        const float4* hp = reinterpret_cast<const float4*>(sh + s*HST);
        float4 p0 = hp[0];
        float4 p1 = hp[1];
        float4 p2 = hp[2];
        float hv[DD] = {p0.x, p0.y, p0.z, p0.w, p1.x, p1.y, p1.z, p1.w, p2.x, p2.y};

        float2 a00 = make_float2(0.f, 0.f), a01 = a00, a10 = a00, a11 = a00;
#pragma unroll
        for (int d = 0; d < DD; d++) {
            float2 h2 = make_float2(hv[d], hv[d]);
            a00 = ffma2(w[0][0][d], h2, a00);
            a01 = ffma2(w[0][1][d], h2, a01);
            a10 = ffma2(w[1][0][d], h2, a10);
            a11 = ffma2(w[1][1][d], h2, a11);
        }
        size_t rowoff = (size_t)(r0 + s) * VV;
        __stcs(reinterpret_cast<float4*>(out + rowoff + vbase),
               make_float4(a00.x, a00.y, a01.x, a01.y));
        __stcs(reinterpret_cast<float4*>(out + rowoff + vbase + 128),
               make_float4(a10.x, a10.y, a11.x, a11.y));
    }
}

// ---------------------------------------------------------------------------
extern "C" void kernel_launch(void* const* d_in, const int* in_sizes, int n_in,
                              void* d_out, int out_size)
{
    const int*   x   = (const int*)  d_in[0];
    const float* emb = (const float*)d_in[1];
    const float* pos = (const float*)d_in[2];
    const float* Wq  = (const float*)d_in[3];
    const float* Wk  = (const float*)d_in[4];
    const float* Wv  = (const float*)d_in[5];
    const float* Wo  = (const float*)d_in[6];
    float* out = (float*)d_out;

    noop_kernel<<<1, 1>>>();   // slot-shift: capture (launch #6) lands on attn
    noop_kernel<<<1, 1>>>();
    qkv_kernel<<<dim3(ROWS / 128, 3), 128>>>(x, emb, pos, Wq, Wk, Wv);
    attn_kernel<<<dim3(64, BB), 256>>>();
    logits_kernel<<<dim3(ROWS / RPB, 25), 160>>>(Wo, out);
}

// round 9
// speedup vs baseline: 1.0726x; 1.0726x over previous
#include <cuda_runtime.h>

#define BB   4
#define SS   2048
#define DD   10
#define VV   32000
#define ROWS (BB*SS)
#define RPB  128       // rows per logits block
#define HST  12        // padded h stride (floats) for LDS.128

// scratch (device globals — no allocation allowed)
__device__ float g_Q[ROWS*DD];     // row-major [b*SS+s][d]
__device__ float g_K[BB*DD*SS];    // d-major  [b][d][s]  -> coalesced lane-t reads
__device__ float g_V[BB*DD*SS];    // d-major  [b][d][s]
__device__ float g_O[ROWS*DD];     // row-major

// packed f32x2 FMA (Blackwell FFMA2)
__device__ __forceinline__ float2 ffma2(float2 a, float2 b, float2 c) {
    float2 d;
    asm("fma.rn.f32x2 %0, %1, %2, %3;"
        : "=l"(reinterpret_cast<unsigned long long&>(d))
        : "l"(reinterpret_cast<unsigned long long&>(a)),
          "l"(reinterpret_cast<unsigned long long&>(b)),
          "l"(reinterpret_cast<unsigned long long&>(c)));
    return d;
}

// two no-ops: keeps the ncu capture slot (launch #6) on attn_kernel
__global__ void noop_kernel() {}

// ---------------------------------------------------------------------------
// Kernel 1: h = emb[x] + pos;  G = h @ W.T  for one of {Q,K,V} per blockIdx.y.
// Q written row-major; K/V written d-major (fixed d, consecutive s across
// threads -> every STG.32 is fully coalesced).
// ---------------------------------------------------------------------------
__global__ void __launch_bounds__(128) qkv_kernel(
    const int* __restrict__ x, const float* __restrict__ emb,
    const float* __restrict__ pos, const float* __restrict__ Wq,
    const float* __restrict__ Wk, const float* __restrict__ Wv)
{
    __shared__ float sw[DD*DD];
    const float* W = (blockIdx.y == 0) ? Wq : (blockIdx.y == 1) ? Wk : Wv;

    if (threadIdx.x < DD*DD/2)
        ((float2*)sw)[threadIdx.x] = __ldg((const float2*)W + threadIdx.x);

    int row = blockIdx.x * 128 + threadIdx.x;
    int s   = row & (SS - 1);
    int b   = row >> 11;
    int tok = x[row];

    float2 h2[5];
    const float2* ep = (const float2*)(emb + tok*DD);
    const float2* pp = (const float2*)(pos + s*DD);
#pragma unroll
    for (int e = 0; e < 5; e++) {
        float2 ee = __ldg(ep + e), qq = __ldg(pp + e);
        h2[e] = make_float2(ee.x + qq.x, ee.y + qq.y);
    }
    __syncthreads();

    float r0v[DD];
#pragma unroll
    for (int d = 0; d < DD; d += 2) {
        float2 s0 = make_float2(0.f, 0.f), s1 = s0;
        const float2* w0 = (const float2*)(sw + d*DD);
        const float2* w1 = (const float2*)(sw + (d+1)*DD);
#pragma unroll
        for (int e = 0; e < 5; e++) {
            s0 = ffma2(h2[e], w0[e], s0);
            s1 = ffma2(h2[e], w1[e], s1);
        }
        r0v[d]   = s0.x + s0.y;
        r0v[d+1] = s1.x + s1.y;
    }

    if (blockIdx.y == 0) {
        float2* go = (float2*)(g_Q + row*DD);
#pragma unroll
        for (int e = 0; e < 5; e++) go[e] = make_float2(r0v[2*e], r0v[2*e+1]);
    } else {
        float* G = (blockIdx.y == 1) ? g_K : g_V;
        size_t base = (size_t)b*DD*SS + s;
#pragma unroll
        for (int d = 0; d < DD; d++) G[base + (size_t)d*SS] = r0v[d];
    }
}

// ---------------------------------------------------------------------------
// Kernel 2: causal attention — R3 structure (warp = 4 rows, lanes split t,
// butterfly combine) but with d-major K/V so every per-iteration load is a
// fully COALESCED warp-LDG.32 (1 line, 1 wavefront, MLP=20) instead of 32
// scattered lines. __launch_bounds__(256,2) forces >=2 blocks/SM.
// Masked t (t > s) contribute exactly 0 (== reference's exp(-1e9/sqrt(d))).
// ---------------------------------------------------------------------------
__global__ void __launch_bounds__(256, 2) attn_kernel()
{
    int b    = blockIdx.y;
    int k    = 63 - blockIdx.x;          // heavy-first
    int warp = threadIdx.x >> 5;
    int lane = threadIdx.x & 31;
    const float inv_sqrt_d = 0.3162277660168379f;
    const float* Kb = g_K + (size_t)b*DD*SS;
    const float* Vb = g_V + (size_t)b*DD*SS;

    int s0 = k * 32 + warp * 4;
    float2 q2[4][5], acc[4][5];
    float  l[4];
#pragma unroll
    for (int r = 0; r < 4; r++) {
        l[r] = 0.f;
        const float2* qp = (const float2*)(g_Q + ((size_t)b*SS + s0 + r)*DD);
#pragma unroll
        for (int e = 0; e < 5; e++) {
            q2[r][e]  = __ldg(qp + e);
            acc[r][e] = make_float2(0.f, 0.f);
        }
    }
    int smax = s0 + 3;
    for (int t = lane; t <= smax; t += 32) {
        float kd[DD], vd[DD];
#pragma unroll
        for (int d = 0; d < DD; d++) kd[d] = __ldg(Kb + (size_t)d*SS + t);
#pragma unroll
        for (int d = 0; d < DD; d++) vd[d] = __ldg(Vb + (size_t)d*SS + t);
        float2 k2[5], v2[5];
#pragma unroll
        for (int e = 0; e < 5; e++) {
            k2[e] = make_float2(kd[2*e], kd[2*e+1]);
            v2[e] = make_float2(vd[2*e], vd[2*e+1]);
        }
#pragma unroll
        for (int r = 0; r < 4; r++) {
            float2 s2 = make_float2(0.f, 0.f);
#pragma unroll
            for (int e = 0; e < 5; e++) s2 = ffma2(q2[r][e], k2[e], s2);
            float sc = s2.x + s2.y;
            if (t <= s0 + r) {
                float ex = __expf(sc * inv_sqrt_d);
                l[r] += ex;
                float2 e2 = make_float2(ex, ex);
#pragma unroll
                for (int e = 0; e < 5; e++) acc[r][e] = ffma2(v2[e], e2, acc[r][e]);
            }
        }
    }
    // warp-wide butterfly reduction
#pragma unroll
    for (int off = 16; off > 0; off >>= 1) {
#pragma unroll
        for (int r = 0; r < 4; r++) {
            l[r] += __shfl_xor_sync(0xffffffffu, l[r], off);
#pragma unroll
            for (int e = 0; e < 5; e++) {
                acc[r][e].x += __shfl_xor_sync(0xffffffffu, acc[r][e].x, off);
                acc[r][e].y += __shfl_xor_sync(0xffffffffu, acc[r][e].y, off);
            }
        }
    }
#pragma unroll
    for (int r = 0; r < 4; r++) {
        float il = 1.f / l[r];
        if (lane < DD) {
            float v = (lane & 1) ? acc[r][lane >> 1].y : acc[r][lane >> 1].x;
            g_O[((size_t)b*SS + s0 + r)*DD + lane] = v * il;
        }
    }
}

// ---------------------------------------------------------------------------
// Kernel 3: logits = out @ Wo.T — EXACT R5 version (best measured: 163.5us,
// DRAM 76%). 3 LDS.128 (padded) + 40 FFMA2 + 2 dense STG.128 per (warp,row).
// ---------------------------------------------------------------------------
__global__ void __launch_bounds__(160) logits_kernel(
    const float* __restrict__ Wo, float* __restrict__ out)
{
    __shared__ float sh[RPB*HST];
    int r0   = blockIdx.x * RPB;
    int tid  = threadIdx.x;
    int warp = tid >> 5;
    int lane = tid & 31;

    for (int i = tid; i < RPB*DD; i += 160) {
        int row = i / DD, d = i - row*DD;
        sh[row*HST + d] = g_O[r0*DD + i];
    }
    __syncthreads();

    int vbase = (blockIdx.y * 5 + warp) * 256 + lane * 4;

    float2 w[2][2][DD];   // [chunk][pair][d]
#pragma unroll
    for (int c = 0; c < 2; c++)
#pragma unroll
        for (int p = 0; p < 2; p++)
#pragma unroll
            for (int d = 0; d < DD; d++) {
                int v = vbase + c*128 + 2*p;
                w[c][p][d].x = __ldg(Wo + (v    )*DD + d);
                w[c][p][d].y = __ldg(Wo + (v + 1)*DD + d);
            }

#pragma unroll 1
    for (int s = 0; s < RPB; s++) {
        const float4* hp = reinterpret_cast<const float4*>(sh + s*HST);
        float4 p0 = hp[0];
        float4 p1 = hp[1];
        float4 p2 = hp[2];
        float hv[DD] = {p0.x, p0.y, p0.z, p0.w, p1.x, p1.y, p1.z, p1.w, p2.x, p2.y};

        float2 a00 = make_float2(0.f, 0.f), a01 = a00, a10 = a00, a11 = a00;
#pragma unroll
        for (int d = 0; d < DD; d++) {
            float2 h2 = make_float2(hv[d], hv[d]);
            a00 = ffma2(w[0][0][d], h2, a00);
            a01 = ffma2(w[0][1][d], h2, a01);
            a10 = ffma2(w[1][0][d], h2, a10);
            a11 = ffma2(w[1][1][d], h2, a11);
        }
        size_t rowoff = (size_t)(r0 + s) * VV;
        __stcs(reinterpret_cast<float4*>(out + rowoff + vbase),
               make_float4(a00.x, a00.y, a01.x, a01.y));
        __stcs(reinterpret_cast<float4*>(out + rowoff + vbase + 128),
               make_float4(a10.x, a10.y, a11.x, a11.y));
    }
}

// ---------------------------------------------------------------------------
extern "C" void kernel_launch(void* const* d_in, const int* in_sizes, int n_in,
                              void* d_out, int out_size)
{
    const int*   x   = (const int*)  d_in[0];
    const float* emb = (const float*)d_in[1];
    const float* pos = (const float*)d_in[2];
    const float* Wq  = (const float*)d_in[3];
    const float* Wk  = (const float*)d_in[4];
    const float* Wv  = (const float*)d_in[5];
    const float* Wo  = (const float*)d_in[6];
    float* out = (float*)d_out;

    noop_kernel<<<1, 1>>>();   // slot-shift: capture (launch #6) lands on attn
    noop_kernel<<<1, 1>>>();
    qkv_kernel<<<dim3(ROWS / 128, 3), 128>>>(x, emb, pos, Wq, Wk, Wv);
    attn_kernel<<<dim3(64, BB), 256>>>();
    logits_kernel<<<dim3(ROWS / RPB, 25), 160>>>(Wo, out);
}

// round 10
// speedup vs baseline: 1.1467x; 1.0691x over previous
#include <cuda_runtime.h>

#define BB   4
#define SS   2048
#define DD   10
#define VV   32000
#define ROWS (BB*SS)
#define RPB  128       // rows per logits block
#define HST  12        // padded h stride (floats) for LDS.128

// scratch (device globals — no allocation allowed)
__device__ float g_Q[ROWS*DD];     // row-major [b*SS+s][d]
__device__ float g_K[BB*DD*SS];    // d-major  [b][d][s]  -> coalesced lane-t reads
__device__ float g_V[BB*DD*SS];    // d-major  [b][d][s]
__device__ float g_O[ROWS*DD];     // row-major

// packed f32x2 FMA (Blackwell FFMA2)
__device__ __forceinline__ float2 ffma2(float2 a, float2 b, float2 c) {
    float2 d;
    asm("fma.rn.f32x2 %0, %1, %2, %3;"
        : "=l"(reinterpret_cast<unsigned long long&>(d))
        : "l"(reinterpret_cast<unsigned long long&>(a)),
          "l"(reinterpret_cast<unsigned long long&>(b)),
          "l"(reinterpret_cast<unsigned long long&>(c)));
    return d;
}

// two no-ops: keeps the ncu capture slot (launch #6) on attn_kernel
__global__ void noop_kernel() {}

// ---------------------------------------------------------------------------
// Kernel 1: h = emb[x] + pos;  G = h @ W.T  for one of {Q,K,V} per blockIdx.y.
// Q row-major; K/V d-major (fixed d, consecutive s -> coalesced STG.32).
// ---------------------------------------------------------------------------
__global__ void __launch_bounds__(128) qkv_kernel(
    const int* __restrict__ x, const float* __restrict__ emb,
    const float* __restrict__ pos, const float* __restrict__ Wq,
    const float* __restrict__ Wk, const float* __restrict__ Wv)
{
    __shared__ float sw[DD*DD];
    const float* W = (blockIdx.y == 0) ? Wq : (blockIdx.y == 1) ? Wk : Wv;

    if (threadIdx.x < DD*DD/2)
        ((float2*)sw)[threadIdx.x] = __ldg((const float2*)W + threadIdx.x);

    int row = blockIdx.x * 128 + threadIdx.x;
    int s   = row & (SS - 1);
    int b   = row >> 11;
    int tok = x[row];

    float2 h2[5];
    const float2* ep = (const float2*)(emb + tok*DD);
    const float2* pp = (const float2*)(pos + s*DD);
#pragma unroll
    for (int e = 0; e < 5; e++) {
        float2 ee = __ldg(ep + e), qq = __ldg(pp + e);
        h2[e] = make_float2(ee.x + qq.x, ee.y + qq.y);
    }
    __syncthreads();

    float r0v[DD];
#pragma unroll
    for (int d = 0; d < DD; d += 2) {
        float2 s0 = make_float2(0.f, 0.f), s1 = s0;
        const float2* w0 = (const float2*)(sw + d*DD);
        const float2* w1 = (const float2*)(sw + (d+1)*DD);
#pragma unroll
        for (int e = 0; e < 5; e++) {
            s0 = ffma2(h2[e], w0[e], s0);
            s1 = ffma2(h2[e], w1[e], s1);
        }
        r0v[d]   = s0.x + s0.y;
        r0v[d+1] = s1.x + s1.y;
    }

    if (blockIdx.y == 0) {
        float2* go = (float2*)(g_Q + row*DD);
#pragma unroll
        for (int e = 0; e < 5; e++) go[e] = make_float2(r0v[2*e], r0v[2*e+1]);
    } else {
        float* G = (blockIdx.y == 1) ? g_K : g_V;
        size_t base = (size_t)b*DD*SS + s;
#pragma unroll
        for (int d = 0; d < DD; d++) G[base + (size_t)d*SS] = r0v[d];
    }
}

// ---------------------------------------------------------------------------
// Kernel 2: causal attention — critical path cut 4x. Block = 8 rows of one
// batch; 8 warps = 2 row-quads x 4 t-quarters. Each warp: 4 rows, lanes
// split its t-quarter (d-major K/V -> coalesced LDG), butterfly-reduce,
// then the 4 quarters combine through shared in fixed order. Heaviest warp
// chain: 16 iters (was 64). Grid (256,4) = 3.5 waves, heavy-first packing.
// Masked t (t > s) contribute exactly 0 (== reference's exp(-1e9/sqrt(d))).
// ---------------------------------------------------------------------------
__global__ void __launch_bounds__(256, 2) attn_kernel()
{
    __shared__ float sp[8][4][12];   // [warp][row][l + 10 acc + pad]
    __shared__ float sm2[8][12];     // combined per group-row

    int b    = blockIdx.y;
    int g    = 255 - blockIdx.x;     // heavy-first
    int w    = threadIdx.x >> 5;
    int lane = threadIdx.x & 31;
    int qd   = w & 1;                // row-quad in group
    int j    = w >> 1;               // t-quarter
    const float inv_sqrt_d = 0.3162277660168379f;
    const float* Kb = g_K + (size_t)b*DD*SS;
    const float* Vb = g_V + (size_t)b*DD*SS;

    int s0g  = g * 8;
    int s0   = s0g + qd * 4;
    int smax = s0 + 3;
    int R    = s0g + 8;                      // causal range of the group
    int C    = ((R + 127) >> 7) << 5;        // quarter chunk, mult of 32
    int tend = min((j + 1) * C - 1, smax);

    float2 q2[4][5], acc[4][5];
    float  l[4];
#pragma unroll
    for (int r = 0; r < 4; r++) {
        l[r] = 0.f;
        const float2* qp = (const float2*)(g_Q + ((size_t)b*SS + s0 + r)*DD);
#pragma unroll
        for (int e = 0; e < 5; e++) {
            q2[r][e]  = __ldg(qp + e);
            acc[r][e] = make_float2(0.f, 0.f);
        }
    }

    for (int t = j*C + lane; t <= tend; t += 32) {
        float kd[DD], vd[DD];
#pragma unroll
        for (int d = 0; d < DD; d++) kd[d] = __ldg(Kb + (size_t)d*SS + t);
#pragma unroll
        for (int d = 0; d < DD; d++) vd[d] = __ldg(Vb + (size_t)d*SS + t);
        float2 k2[5], v2[5];
#pragma unroll
        for (int e = 0; e < 5; e++) {
            k2[e] = make_float2(kd[2*e], kd[2*e+1]);
            v2[e] = make_float2(vd[2*e], vd[2*e+1]);
        }
#pragma unroll
        for (int r = 0; r < 4; r++) {
            float2 s2 = make_float2(0.f, 0.f);
#pragma unroll
            for (int e = 0; e < 5; e++) s2 = ffma2(q2[r][e], k2[e], s2);
            float sc = s2.x + s2.y;
            if (t <= s0 + r) {
                float ex = __expf(sc * inv_sqrt_d);
                l[r] += ex;
                float2 e2 = make_float2(ex, ex);
#pragma unroll
                for (int e = 0; e < 5; e++) acc[r][e] = ffma2(v2[e], e2, acc[r][e]);
            }
        }
    }
    // warp-wide butterfly reduction (all lanes end with totals)
#pragma unroll
    for (int off = 16; off > 0; off >>= 1) {
#pragma unroll
        for (int r = 0; r < 4; r++) {
            l[r] += __shfl_xor_sync(0xffffffffu, l[r], off);
#pragma unroll
            for (int e = 0; e < 5; e++) {
                acc[r][e].x += __shfl_xor_sync(0xffffffffu, acc[r][e].x, off);
                acc[r][e].y += __shfl_xor_sync(0xffffffffu, acc[r][e].y, off);
            }
        }
    }
    // stage this warp's partials (lanes 0..10: l, acc[0..9])
#pragma unroll
    for (int r = 0; r < 4; r++) {
        if (lane < 11) {
            float v;
            if (lane == 0) v = l[r];
            else {
                int d = lane - 1;
                v = (d & 1) ? acc[r][d >> 1].y : acc[r][d >> 1].x;
            }
            sp[w][r][lane] = v;
        }
    }
    __syncthreads();

    // combine the 4 t-quarters per group-row (fixed order -> deterministic)
    for (int i = threadIdx.x; i < 88; i += 256) {
        int rg = i / 11, c = i - rg*11;
        int qq = rg >> 2, rr = rg & 3;
        sm2[rg][c] = ((sp[0 + qq][rr][c]  + sp[2 + qq][rr][c])
                   +  (sp[4 + qq][rr][c]  + sp[6 + qq][rr][c]));
    }
    __syncthreads();

    for (int i = threadIdx.x; i < 80; i += 256) {
        int rg = i / 10, d = i - rg*10;
        g_O[((size_t)b*SS + s0g + rg)*DD + d] = sm2[rg][1 + d] / sm2[rg][0];
    }
}

// ---------------------------------------------------------------------------
// Kernel 3: logits = out @ Wo.T — EXACT R5 version (best measured: 163.5us,
// DRAM 76%). 3 LDS.128 (padded) + 40 FFMA2 + 2 dense STG.128 per (warp,row).
// ---------------------------------------------------------------------------
__global__ void __launch_bounds__(160) logits_kernel(
    const float* __restrict__ Wo, float* __restrict__ out)
{
    __shared__ float sh[RPB*HST];
    int r0   = blockIdx.x * RPB;
    int tid  = threadIdx.x;
    int warp = tid >> 5;
    int lane = tid & 31;

    for (int i = tid; i < RPB*DD; i += 160) {
        int row = i / DD, d = i - row*DD;
        sh[row*HST + d] = g_O[r0*DD + i];
    }
    __syncthreads();

    int vbase = (blockIdx.y * 5 + warp) * 256 + lane * 4;

    float2 w[2][2][DD];   // [chunk][pair][d]
#pragma unroll
    for (int c = 0; c < 2; c++)
#pragma unroll
        for (int p = 0; p < 2; p++)
#pragma unroll
            for (int d = 0; d < DD; d++) {
                int v = vbase + c*128 + 2*p;
                w[c][p][d].x = __ldg(Wo + (v    )*DD + d);
                w[c][p][d].y = __ldg(Wo + (v + 1)*DD + d);
            }

#pragma unroll 1
    for (int s = 0; s < RPB; s++) {
        const float4* hp = reinterpret_cast<const float4*>(sh + s*HST);
        float4 p0 = hp[0];
        float4 p1 = hp[1];
        float4 p2 = hp[2];
        float hv[DD] = {p0.x, p0.y, p0.z, p0.w, p1.x, p1.y, p1.z, p1.w, p2.x, p2.y};

        float2 a00 = make_float2(0.f, 0.f), a01 = a00, a10 = a00, a11 = a00;
#pragma unroll
        for (int d = 0; d < DD; d++) {
            float2 h2 = make_float2(hv[d], hv[d]);
            a00 = ffma2(w[0][0][d], h2, a00);
            a01 = ffma2(w[0][1][d], h2, a01);
            a10 = ffma2(w[1][0][d], h2, a10);
            a11 = ffma2(w[1][1][d], h2, a11);
        }
        size_t rowoff = (size_t)(r0 + s) * VV;
        __stcs(reinterpret_cast<float4*>(out + rowoff + vbase),
               make_float4(a00.x, a00.y, a01.x, a01.y));
        __stcs(reinterpret_cast<float4*>(out + rowoff + vbase + 128),
               make_float4(a10.x, a10.y, a11.x, a11.y));
    }
}

// ---------------------------------------------------------------------------
extern "C" void kernel_launch(void* const* d_in, const int* in_sizes, int n_in,
                              void* d_out, int out_size)
{
    const int*   x   = (const int*)  d_in[0];
    const float* emb = (const float*)d_in[1];
    const float* pos = (const float*)d_in[2];
    const float* Wq  = (const float*)d_in[3];
    const float* Wk  = (const float*)d_in[4];
    const float* Wv  = (const float*)d_in[5];
    const float* Wo  = (const float*)d_in[6];
    float* out = (float*)d_out;

    noop_kernel<<<1, 1>>>();   // slot-shift: capture (launch #6) lands on attn
    noop_kernel<<<1, 1>>>();
    qkv_kernel<<<dim3(ROWS / 128, 3), 128>>>(x, emb, pos, Wq, Wk, Wv);
    attn_kernel<<<dim3(256, BB), 256>>>();
    logits_kernel<<<dim3(ROWS / RPB, 25), 160>>>(Wo, out);
}

// round 11
// speedup vs baseline: 1.1517x; 1.0043x over previous
#include <cuda_runtime.h>

#define BB   4
#define SS   2048
#define DD   10
#define VV   32000
#define ROWS (BB*SS)
#define RPB  128       // rows per logits block
#define HST  12        // padded h stride (floats) for LDS.128

// scratch (device globals — no allocation allowed)
__device__ float  g_Q [ROWS*DD];      // row-major [b*SS+s][d]
__device__ float2 g_KV[BB*10*SS];     // [b][plane][s] f32x2: planes 0-4 = K pairs, 5-9 = V pairs
__device__ float  g_O [ROWS*DD];      // row-major

// packed f32x2 FMA (Blackwell FFMA2)
__device__ __forceinline__ float2 ffma2(float2 a, float2 b, float2 c) {
    float2 d;
    asm("fma.rn.f32x2 %0, %1, %2, %3;"
        : "=l"(reinterpret_cast<unsigned long long&>(d))
        : "l"(reinterpret_cast<unsigned long long&>(a)),
          "l"(reinterpret_cast<unsigned long long&>(b)),
          "l"(reinterpret_cast<unsigned long long&>(c)));
    return d;
}

// two no-ops: keeps the ncu capture slot (launch #6) on attn_kernel
__global__ void noop_kernel() {}

// ---------------------------------------------------------------------------
// Kernel 1: h = emb[x] + pos;  G = h @ W.T  for one of {Q,K,V} per blockIdx.y.
// Q row-major; K/V written as f32x2 planes [b][plane][s] (lane stride 8B,
// coalesced) so attn loads whole pairs with immediate-offset LDG.64.
// ---------------------------------------------------------------------------
__global__ void __launch_bounds__(128) qkv_kernel(
    const int* __restrict__ x, const float* __restrict__ emb,
    const float* __restrict__ pos, const float* __restrict__ Wq,
    const float* __restrict__ Wk, const float* __restrict__ Wv)
{
    __shared__ float sw[DD*DD];
    const float* W = (blockIdx.y == 0) ? Wq : (blockIdx.y == 1) ? Wk : Wv;

    if (threadIdx.x < DD*DD/2)
        ((float2*)sw)[threadIdx.x] = __ldg((const float2*)W + threadIdx.x);

    int row = blockIdx.x * 128 + threadIdx.x;
    int s   = row & (SS - 1);
    int b   = row >> 11;
    int tok = x[row];

    float2 h2[5];
    const float2* ep = (const float2*)(emb + tok*DD);
    const float2* pp = (const float2*)(pos + s*DD);
#pragma unroll
    for (int e = 0; e < 5; e++) {
        float2 ee = __ldg(ep + e), qq = __ldg(pp + e);
        h2[e] = make_float2(ee.x + qq.x, ee.y + qq.y);
    }
    __syncthreads();

    float r0v[DD];
#pragma unroll
    for (int d = 0; d < DD; d += 2) {
        float2 s0 = make_float2(0.f, 0.f), s1 = s0;
        const float2* w0 = (const float2*)(sw + d*DD);
        const float2* w1 = (const float2*)(sw + (d+1)*DD);
#pragma unroll
        for (int e = 0; e < 5; e++) {
            s0 = ffma2(h2[e], w0[e], s0);
            s1 = ffma2(h2[e], w1[e], s1);
        }
        r0v[d]   = s0.x + s0.y;
        r0v[d+1] = s1.x + s1.y;
    }

    if (blockIdx.y == 0) {
        float2* go = (float2*)(g_Q + row*DD);
#pragma unroll
        for (int e = 0; e < 5; e++) go[e] = make_float2(r0v[2*e], r0v[2*e+1]);
    } else {
        int pbase = (blockIdx.y == 1) ? 0 : 5;
        float2* G2 = g_KV + (size_t)b*10*SS + s;
#pragma unroll
        for (int e = 0; e < 5; e++)
            G2[(size_t)(pbase + e)*SS] = make_float2(r0v[2*e], r0v[2*e+1]);
    }
}

// ---------------------------------------------------------------------------
// Kernel 2: causal attention — R10 structure (block = 8 rows, 8 warps =
// 2 row-quads x 4 t-quarters, butterfly + shared combine) with f32x2-packed
// K/V: 10 immediate-offset LDG.64 per iteration, no pack MOVs (~30% fewer
// instructions per iter; this kernel is pure issue-bound).
// Masked t (t > s) contribute exactly 0 (== reference's exp(-1e9/sqrt(d))).
// ---------------------------------------------------------------------------
__global__ void __launch_bounds__(256, 2) attn_kernel()
{
    __shared__ float sp[8][4][12];   // [warp][row][l + 10 acc + pad]
    __shared__ float sm2[8][12];     // combined per group-row

    int b    = blockIdx.y;
    int g    = 255 - blockIdx.x;     // heavy-first
    int w    = threadIdx.x >> 5;
    int lane = threadIdx.x & 31;
    int qd   = w & 1;                // row-quad in group
    int j    = w >> 1;               // t-quarter
    const float inv_sqrt_d = 0.3162277660168379f;
    const float2* KVb = g_KV + (size_t)b*10*SS;

    int s0g  = g * 8;
    int s0   = s0g + qd * 4;
    int smax = s0 + 3;
    int R    = s0g + 8;                      // causal range of the group
    int C    = ((R + 127) >> 7) << 5;        // quarter chunk, mult of 32
    int tend = min((j + 1) * C - 1, smax);

    float2 q2[4][5], acc[4][5];
    float  l[4];
#pragma unroll
    for (int r = 0; r < 4; r++) {
        l[r] = 0.f;
        const float2* qp = (const float2*)(g_Q + ((size_t)b*SS + s0 + r)*DD);
#pragma unroll
        for (int e = 0; e < 5; e++) {
            q2[r][e]  = __ldg(qp + e);
            acc[r][e] = make_float2(0.f, 0.f);
        }
    }

    for (int t = j*C + lane; t <= tend; t += 32) {
        const float2* kv = KVb + t;
        float2 k2[5], v2[5];
#pragma unroll
        for (int e = 0; e < 5; e++) k2[e] = __ldg(kv + (size_t)e*SS);
#pragma unroll
        for (int e = 0; e < 5; e++) v2[e] = __ldg(kv + (size_t)(5+e)*SS);
#pragma unroll
        for (int r = 0; r < 4; r++) {
            float2 s2 = make_float2(0.f, 0.f);
#pragma unroll
            for (int e = 0; e < 5; e++) s2 = ffma2(q2[r][e], k2[e], s2);
            float sc = s2.x + s2.y;
            if (t <= s0 + r) {
                float ex = __expf(sc * inv_sqrt_d);
                l[r] += ex;
                float2 e2 = make_float2(ex, ex);
#pragma unroll
                for (int e = 0; e < 5; e++) acc[r][e] = ffma2(v2[e], e2, acc[r][e]);
            }
        }
    }
    // warp-wide butterfly reduction
#pragma unroll
    for (int off = 16; off > 0; off >>= 1) {
#pragma unroll
        for (int r = 0; r < 4; r++) {
            l[r] += __shfl_xor_sync(0xffffffffu, l[r], off);
#pragma unroll
            for (int e = 0; e < 5; e++) {
                acc[r][e].x += __shfl_xor_sync(0xffffffffu, acc[r][e].x, off);
                acc[r][e].y += __shfl_xor_sync(0xffffffffu, acc[r][e].y, off);
            }
        }
    }
    // stage this warp's partials (lanes 0..10: l, acc[0..9])
#pragma unroll
    for (int r = 0; r < 4; r++) {
        if (lane < 11) {
            float v;
            if (lane == 0) v = l[r];
            else {
                int d = lane - 1;
                v = (d & 1) ? acc[r][d >> 1].y : acc[r][d >> 1].x;
            }
            sp[w][r][lane] = v;
        }
    }
    __syncthreads();

    // combine the 4 t-quarters per group-row (fixed order -> deterministic)
    for (int i = threadIdx.x; i < 88; i += 256) {
        int rg = i / 11, c = i - rg*11;
        int qq = rg >> 2, rr = rg & 3;
        sm2[rg][c] = ((sp[0 + qq][rr][c]  + sp[2 + qq][rr][c])
                   +  (sp[4 + qq][rr][c]  + sp[6 + qq][rr][c]));
    }
    __syncthreads();

    for (int i = threadIdx.x; i < 80; i += 256) {
        int rg = i / 10, d = i - rg*10;
        g_O[((size_t)b*SS + s0g + rg)*DD + d] = sm2[rg][1 + d] / sm2[rg][0];
    }
}

// ---------------------------------------------------------------------------
// Kernel 3: logits = out @ Wo.T — EXACT R5 version (best measured: 163.5us,
// DRAM 76%). 3 LDS.128 (padded) + 40 FFMA2 + 2 dense STG.128 per (warp,row).
// ---------------------------------------------------------------------------
__global__ void __launch_bounds__(160) logits_kernel(
    const float* __restrict__ Wo, float* __restrict__ out)
{
    __shared__ float sh[RPB*HST];
    int r0   = blockIdx.x * RPB;
    int tid  = threadIdx.x;
    int warp = tid >> 5;
    int lane = tid & 31;

    for (int i = tid; i < RPB*DD; i += 160) {
        int row = i / DD, d = i - row*DD;
        sh[row*HST + d] = g_O[r0*DD + i];
    }
    __syncthreads();

    int vbase = (blockIdx.y * 5 + warp) * 256 + lane * 4;

    float2 w[2][2][DD];   // [chunk][pair][d]
#pragma unroll
    for (int c = 0; c < 2; c++)
#pragma unroll
        for (int p = 0; p < 2; p++)
#pragma unroll
            for (int d = 0; d < DD; d++) {
                int v = vbase + c*128 + 2*p;
                w[c][p][d].x = __ldg(Wo + (v    )*DD + d);
                w[c][p][d].y = __ldg(Wo + (v + 1)*DD + d);
            }

#pragma unroll 1
    for (int s = 0; s < RPB; s++) {
        const float4* hp = reinterpret_cast<const float4*>(sh + s*HST);
        float4 p0 = hp[0];
        float4 p1 = hp[1];
        float4 p2 = hp[2];
        float hv[DD] = {p0.x, p0.y, p0.z, p0.w, p1.x, p1.y, p1.z, p1.w, p2.x, p2.y};

        float2 a00 = make_float2(0.f, 0.f), a01 = a00, a10 = a00, a11 = a00;
#pragma unroll
        for (int d = 0; d < DD; d++) {
            float2 h2 = make_float2(hv[d], hv[d]);
            a00 = ffma2(w[0][0][d], h2, a00);
            a01 = ffma2(w[0][1][d], h2, a01);
            a10 = ffma2(w[1][0][d], h2, a10);
            a11 = ffma2(w[1][1][d], h2, a11);
        }
        size_t rowoff = (size_t)(r0 + s) * VV;
        __stcs(reinterpret_cast<float4*>(out + rowoff + vbase),
               make_float4(a00.x, a00.y, a01.x, a01.y));
        __stcs(reinterpret_cast<float4*>(out + rowoff + vbase + 128),
               make_float4(a10.x, a10.y, a11.x, a11.y));
    }
}

// ---------------------------------------------------------------------------
extern "C" void kernel_launch(void* const* d_in, const int* in_sizes, int n_in,
                              void* d_out, int out_size)
{
    const int*   x   = (const int*)  d_in[0];
    const float* emb = (const float*)d_in[1];
    const float* pos = (const float*)d_in[2];
    const float* Wq  = (const float*)d_in[3];
    const float* Wk  = (const float*)d_in[4];
    const float* Wv  = (const float*)d_in[5];
    const float* Wo  = (const float*)d_in[6];
    float* out = (float*)d_out;

    noop_kernel<<<1, 1>>>();   // slot-shift: capture (launch #6) lands on attn
    noop_kernel<<<1, 1>>>();
    qkv_kernel<<<dim3(ROWS / 128, 3), 128>>>(x, emb, pos, Wq, Wk, Wv);
    attn_kernel<<<dim3(256, BB), 256>>>();
    logits_kernel<<<dim3(ROWS / RPB, 25), 160>>>(Wo, out);
}